// round 10
// baseline (speedup 1.0000x reference)
#include <cuda_runtime.h>
#include <cuda_fp16.h>
#include <cstdint>

#define NN 50000
#define F1 256
#define F2 128
#define EMAX 2000000
#define SCAN_B 1024
#define NBLK ((NN + SCAN_B - 1) / SCAN_B)   // 49

// -------- scratch (static device globals; no allocation) --------
__device__ int g_deg[NN];
__device__ int g_off[NN + 1];
__device__ int g_cur[NN];
__device__ int g_bsum[NBLK];
__device__ int g_srcs[EMAX];
__device__ __align__(16) float  g_dinv[NN];
__device__ __align__(16) __half g_hx [(size_t)NN * F1];   // fp16 x
__device__ __align__(16) __half g_hw1[256 * F1];          // fp16 W1
__device__ __align__(16) __half g_hw2[256 * F2];          // fp16 W2
__device__ __align__(16) __half g_hh1[(size_t)NN * F1];   // fp16 (x@W1)  UNSCALED
__device__ __align__(16) __half g_h1h[(size_t)NN * F1];   // fp16 relu'd layer-1 out
__device__ __align__(16) __half g_hh2[(size_t)NN * F2];   // fp16 (h1@W2)*dinv
__device__ int g_is64;

__device__ __forceinline__ uint32_t smem_u32(const void* p) {
    uint32_t a;
    asm("{ .reg .u64 t; cvta.to.shared.u64 t, %1; cvt.u32.u64 %0, t; }" : "=r"(a) : "l"(p));
    return a;
}

#define MMA16816(d, a0, a1, a2, a3, b0, b1)                                   \
    asm volatile(                                                             \
        "mma.sync.aligned.m16n8k16.row.col.f32.f16.f16.f32 "                  \
        "{%0,%1,%2,%3}, {%4,%5,%6,%7}, {%8,%9}, {%0,%1,%2,%3};"               \
        : "+f"((d)[0]), "+f"((d)[1]), "+f"((d)[2]), "+f"((d)[3])              \
        : "r"(a0), "r"(a1), "r"(a2), "r"(a3), "r"(b0), "r"(b1))

#define LDSM_X4(r0, r1, r2, r3, addr)                                         \
    asm volatile("ldmatrix.sync.aligned.m8n8.x4.shared.b16 {%0,%1,%2,%3}, [%4];" \
        : "=r"(r0), "=r"(r1), "=r"(r2), "=r"(r3) : "r"(addr))

#define LDSM_X4_T(r0, r1, r2, r3, addr)                                       \
    asm volatile("ldmatrix.sync.aligned.m8n8.x4.trans.shared.b16 {%0,%1,%2,%3}, [%4];" \
        : "=r"(r0), "=r"(r1), "=r"(r2), "=r"(r3) : "r"(addr))

// -------- edge dtype detection (int64 vs int32) --------
__global__ void k_detect(const int* __restrict__ w, int nwords) {
    __shared__ int ok;
    if (threadIdx.x == 0) ok = 1;
    __syncthreads();
    for (int i = threadIdx.x; i < nwords / 2; i += blockDim.x)
        if (w[2 * i + 1] != 0) ok = 0;   // benign race
    __syncthreads();
    if (threadIdx.x == 0) g_is64 = ok;
}
__device__ __forceinline__ int edge_at(const void* p, int i, int is64) {
    if (is64) return (int)((const long long*)p)[i];
    return ((const int*)p)[i];
}

__global__ void k_zeroint(int* __restrict__ p, int n) {
    int i = blockIdx.x * blockDim.x + threadIdx.x;
    if (i < n) p[i] = 0;
}
__global__ void k_edgedeg(const void* __restrict__ ei, int* __restrict__ deg, int E) {
    int i = blockIdx.x * blockDim.x + threadIdx.x;
    if (i >= E) return;
    int d = edge_at(ei, E + i, g_is64);
    atomicAdd(deg + d, 1);
}

// -------- fused fp32 -> fp16 bulk convert (x, W1, W2 in one launch) --------
__global__ void k_f2h3(const float4* __restrict__ sx, uint2* __restrict__ dx, int nx,
                       const float4* __restrict__ s1, uint2* __restrict__ d1, int n1,
                       const float4* __restrict__ s2, uint2* __restrict__ d2, int n2)
{
    int i = blockIdx.x * blockDim.x + threadIdx.x;
    const float4* s; uint2* d; int j;
    if (i < nx)                { s = sx; d = dx; j = i; }
    else if (i < nx + n1)      { s = s1; d = d1; j = i - nx; }
    else if (i < nx + n1 + n2) { s = s2; d = d2; j = i - nx - n1; }
    else return;
    float4 v = s[j];
    __half2 h0 = __floats2half2_rn(v.x, v.y);
    __half2 h1 = __floats2half2_rn(v.z, v.w);
    uint2 o;
    o.x = *(uint32_t*)&h0;
    o.y = *(uint32_t*)&h1;
    d[j] = o;
}

// -------- 3-phase parallel exclusive scan --------
__global__ __launch_bounds__(SCAN_B) void k_scan1(
    const int* __restrict__ deg, int* __restrict__ off, int* __restrict__ bsum)
{
    __shared__ int sh[SCAN_B];
    int t = threadIdx.x;
    int idx = blockIdx.x * SCAN_B + t;
    int v = (idx < NN) ? deg[idx] : 0;
    sh[t] = v;
    __syncthreads();
#pragma unroll
    for (int d = 1; d < SCAN_B; d <<= 1) {
        int u = 0;
        if (t >= d) u = sh[t - d];
        __syncthreads();
        if (t >= d) sh[t] += u;
        __syncthreads();
    }
    if (idx < NN) off[idx] = sh[t] - v;
    if (t == SCAN_B - 1) bsum[blockIdx.x] = sh[t];
}
__global__ void k_scan2(int* __restrict__ bsum, int* __restrict__ off_last) {
    __shared__ int sh[64];
    int t = threadIdx.x;
    int v = (t < NBLK) ? bsum[t] : 0;
    sh[t] = v;
    __syncthreads();
#pragma unroll
    for (int d = 1; d < 64; d <<= 1) {
        int u = 0;
        if (t >= d) u = sh[t - d];
        __syncthreads();
        if (t >= d) sh[t] += u;
        __syncthreads();
    }
    if (t < NBLK) bsum[t] = sh[t] - v;
    if (t == 63) *off_last = sh[63];
}
__global__ void k_scan3(int* __restrict__ off, int* __restrict__ cur,
                        const int* __restrict__ bsum, const int* __restrict__ deg,
                        float* __restrict__ dinv)
{
    int idx = blockIdx.x * SCAN_B + threadIdx.x;
    if (idx >= NN) return;
    int o = off[idx] + bsum[blockIdx.x];
    off[idx] = o;
    cur[idx] = o;
    dinv[idx] = rsqrtf((float)deg[idx] + 1.0f);
}

__global__ void k_bucket(const void* __restrict__ ei, int* __restrict__ cur,
                         int* __restrict__ srcs, int E) {
    int i = blockIdx.x * blockDim.x + threadIdx.x;
    if (i >= E) return;
    int is64 = g_is64;
    int s = edge_at(ei, i, is64);
    int d = edge_at(ei, E + i, is64);
    int p = atomicAdd(cur + d, 1);
    srcs[p] = s;
}

// ======== fp16 HMMA GEMM: Ch = half((Ah@Bh) [* dinv[row]]),  K=256 ========
// dinv == nullptr -> unscaled output (layer-1; dinv deferred into the gather).
__global__ __launch_bounds__(256) void k_gemm_h(
    const __half* __restrict__ Ah, const __half* __restrict__ Bh,
    const float* __restrict__ dinv, __half* __restrict__ Ch, int M, int N)
{
    constexpr int K = 256;
    constexpr int LDA = 40;                 // halfs: 32 + 8 pad (80B stride)
    constexpr int LDB = 136;                // halfs: 128 + 8 pad (272B stride)
    __shared__ __half As[2][128][LDA];
    __shared__ __half Bs[2][32][LDB];

    int tid = threadIdx.x;
    int w = tid >> 5;
    int lane = tid & 31;
    int gid = lane >> 2;
    int tig = lane & 3;
    int warp_m = w >> 2;                    // 0..1
    int warp_n = w & 3;                     // 0..3
    int row0 = blockIdx.y * 128;
    int col0 = blockIdx.x * 128;

    uint32_t asb = smem_u32(&As[0][0][0]);
    uint32_t bsb = smem_u32(&Bs[0][0][0]);

    float acc[4][4][4];
#pragma unroll
    for (int mt = 0; mt < 4; mt++)
#pragma unroll
        for (int nt = 0; nt < 4; nt++)
#pragma unroll
            for (int q = 0; q < 4; q++) acc[mt][nt][q] = 0.f;

    uint4 ra[2], rb[2];

    auto ldregs = [&](int kt) {
#pragma unroll
        for (int i = 0; i < 2; i++) {
            int u = tid + (i << 8);
            int r = u >> 2, c = (u & 3) * 8;
            int grow = row0 + r;
            ra[i] = (grow < M) ? *(const uint4*)(Ah + (size_t)grow * K + kt + c)
                               : make_uint4(0u, 0u, 0u, 0u);
            int k = u >> 4, cb = (u & 15) * 8;
            rb[i] = *(const uint4*)(Bh + (size_t)(kt + k) * N + col0 + cb);
        }
    };
    auto sts = [&](int b) {
#pragma unroll
        for (int i = 0; i < 2; i++) {
            int u = tid + (i << 8);
            *(uint4*)&As[b][u >> 2][(u & 3) * 8] = ra[i];
            *(uint4*)&Bs[b][u >> 4][(u & 15) * 8] = rb[i];
        }
    };
    auto mmabuf = [&](int b) {
#pragma unroll
        for (int k2 = 0; k2 < 32; k2 += 16) {
            uint32_t bf[4][2];
#pragma unroll
            for (int np = 0; np < 2; np++) {
                int brow = k2 + ((lane >> 3) & 1) * 8 + (lane & 7);
                int bcol = warp_n * 32 + np * 16 + (lane >> 4) * 8;
                uint32_t ad = bsb + (uint32_t)(((b << 5) + brow) * LDB + bcol) * 2;
                LDSM_X4_T(bf[np * 2][0], bf[np * 2][1], bf[np * 2 + 1][0], bf[np * 2 + 1][1], ad);
            }
#pragma unroll
            for (int mt = 0; mt < 4; mt++) {
                int arow = warp_m * 64 + mt * 16 + (lane & 15);
                int kc = k2 + (lane >> 4) * 8;
                uint32_t ad = asb + (uint32_t)(((b << 7) + arow) * LDA + kc) * 2;
                uint32_t a0, a1, a2, a3;
                LDSM_X4(a0, a1, a2, a3, ad);
#pragma unroll
                for (int nt = 0; nt < 4; nt++)
                    MMA16816(acc[mt][nt], a0, a1, a2, a3, bf[nt][0], bf[nt][1]);
            }
        }
    };

    ldregs(0);
    sts(0);
    __syncthreads();
#pragma unroll
    for (int ch = 0; ch < K / 32; ch++) {
        if (ch < K / 32 - 1) ldregs((ch + 1) * 32);
        mmabuf(ch & 1);
        if (ch < K / 32 - 1) sts((ch + 1) & 1);
        __syncthreads();
    }

#pragma unroll
    for (int mt = 0; mt < 4; mt++) {
        int r0 = row0 + warp_m * 64 + mt * 16 + gid;
        int r1 = r0 + 8;
        float s0 = dinv ? ((r0 < M) ? dinv[r0] : 0.f) : 1.f;
        float s1 = dinv ? ((r1 < M) ? dinv[r1] : 0.f) : 1.f;
#pragma unroll
        for (int nt = 0; nt < 4; nt++) {
            int c = col0 + warp_n * 32 + nt * 8 + tig * 2;
            if (r0 < M) {
                __half2 h = __floats2half2_rn(acc[mt][nt][0] * s0, acc[mt][nt][1] * s0);
                *(__half2*)(Ch + (size_t)r0 * N + c) = h;
            }
            if (r1 < M) {
                __half2 h = __floats2half2_rn(acc[mt][nt][2] * s1, acc[mt][nt][3] * s1);
                *(__half2*)(Ch + (size_t)r1 * N + c) = h;
            }
        }
    }
}

// -------- CSR gather-reduce over fp16 features, fp32 accumulate --------
// OUTH: fp16 output. WSRC: features are unscaled -> weight each row by dinv[src].
template <int FH, bool RELU, bool OUTH, bool WSRC>
__global__ __launch_bounds__(256) void k_gather_h(
    const int* __restrict__ off, const int* __restrict__ srcs,
    const __half* __restrict__ hsh, const float* __restrict__ dinv,
    const float* __restrict__ bias, void* __restrict__ outv)
{
    constexpr int F = 32 * FH;
    int node = (blockIdx.x * blockDim.x + threadIdx.x) >> 5;
    int lane = threadIdx.x & 31;
    if (node >= NN) return;
    const __half* base = hsh + lane * FH;

    float acc[FH];
#pragma unroll
    for (int j = 0; j < FH; j++) acc[j] = 0.f;

    auto accum = [&](int s, float wgt) {
        const __half* p = base + (size_t)s * F;
        if (FH == 8) {
            uint4 v = *(const uint4*)p;
            float2 f;
            f = __half22float2(*(__half2*)&v.x);
            if (WSRC) { acc[0] = fmaf(f.x, wgt, acc[0]); acc[1] = fmaf(f.y, wgt, acc[1]); }
            else      { acc[0] += f.x; acc[1] += f.y; }
            f = __half22float2(*(__half2*)&v.y);
            if (WSRC) { acc[2] = fmaf(f.x, wgt, acc[2]); acc[3] = fmaf(f.y, wgt, acc[3]); }
            else      { acc[2] += f.x; acc[3] += f.y; }
            f = __half22float2(*(__half2*)&v.z);
            if (WSRC) { acc[4] = fmaf(f.x, wgt, acc[4]); acc[5] = fmaf(f.y, wgt, acc[5]); }
            else      { acc[4] += f.x; acc[5] += f.y; }
            f = __half22float2(*(__half2*)&v.w);
            if (WSRC) { acc[6] = fmaf(f.x, wgt, acc[6]); acc[7] = fmaf(f.y, wgt, acc[7]); }
            else      { acc[6] += f.x; acc[7] += f.y; }
        } else {
            uint2 v = *(const uint2*)p;
            float2 f;
            f = __half22float2(*(__half2*)&v.x);
            if (WSRC) { acc[0] = fmaf(f.x, wgt, acc[0]); acc[1] = fmaf(f.y, wgt, acc[1]); }
            else      { acc[0] += f.x; acc[1] += f.y; }
            f = __half22float2(*(__half2*)&v.y);
            if (WSRC) { acc[2] = fmaf(f.x, wgt, acc[2]); acc[3] = fmaf(f.y, wgt, acc[3]); }
            else      { acc[2] += f.x; acc[3] += f.y; }
        }
    };

    float sc = dinv[node];
    accum(node, sc);                               // self loop (weight dinv[node] if WSRC)
    int e = off[node], end = off[node + 1];
    for (; e + 4 <= end; e += 4) {
        int s0 = srcs[e], s1 = srcs[e + 1], s2 = srcs[e + 2], s3 = srcs[e + 3];
        float w0 = 1.f, w1 = 1.f, w2 = 1.f, w3 = 1.f;
        if (WSRC) { w0 = dinv[s0]; w1 = dinv[s1]; w2 = dinv[s2]; w3 = dinv[s3]; }
        accum(s0, w0); accum(s1, w1); accum(s2, w2); accum(s3, w3);
    }
    for (; e < end; e++) {
        int s = srcs[e];
        accum(s, WSRC ? dinv[s] : 1.f);
    }

    const float* bp = bias + lane * FH;
    float o[FH];
#pragma unroll
    for (int j = 0; j < FH; j += 4) {
        float4 b = *(const float4*)(bp + j);
        o[j + 0] = sc * acc[j + 0] + b.x;
        o[j + 1] = sc * acc[j + 1] + b.y;
        o[j + 2] = sc * acc[j + 2] + b.z;
        o[j + 3] = sc * acc[j + 3] + b.w;
        if (RELU) {
            o[j + 0] = fmaxf(o[j + 0], 0.f); o[j + 1] = fmaxf(o[j + 1], 0.f);
            o[j + 2] = fmaxf(o[j + 2], 0.f); o[j + 3] = fmaxf(o[j + 3], 0.f);
        }
    }
    if (OUTH) {
        __half* dst = (__half*)outv + (size_t)node * F + lane * FH;
#pragma unroll
        for (int j = 0; j < FH; j += 4) {
            __half2 h0 = __floats2half2_rn(o[j + 0], o[j + 1]);
            __half2 h1 = __floats2half2_rn(o[j + 2], o[j + 3]);
            uint2 hp;
            hp.x = *(uint32_t*)&h0;
            hp.y = *(uint32_t*)&h1;
            *(uint2*)(dst + j) = hp;
        }
    } else {
        float* dst = (float*)outv + (size_t)node * F + lane * FH;
#pragma unroll
        for (int j = 0; j < FH; j += 4) {
            float4 v = make_float4(o[j + 0], o[j + 1], o[j + 2], o[j + 3]);
            *(float4*)(dst + j) = v;
        }
    }
}

extern "C" void kernel_launch(void* const* d_in, const int* in_sizes, int n_in,
                              void* d_out, int out_size)
{
    const float* x  = (const float*)d_in[0];
    const void*  ei = d_in[1];
    const float* W1 = (const float*)d_in[2];
    const float* b1 = (const float*)d_in[3];
    const float* W2 = (const float*)d_in[4];
    const float* b2 = (const float*)d_in[5];
    const int E = in_sizes[1] / 2;
    const int n = NN;

    int *deg, *off, *cur, *srcs, *bsum;
    float *dinv;
    __half *hx, *hw1, *hw2, *hh1, *h1h, *hh2;
    cudaGetSymbolAddress((void**)&deg,  g_deg);
    cudaGetSymbolAddress((void**)&off,  g_off);
    cudaGetSymbolAddress((void**)&cur,  g_cur);
    cudaGetSymbolAddress((void**)&srcs, g_srcs);
    cudaGetSymbolAddress((void**)&bsum, g_bsum);
    cudaGetSymbolAddress((void**)&dinv, g_dinv);
    cudaGetSymbolAddress((void**)&hx,   g_hx);
    cudaGetSymbolAddress((void**)&hw1,  g_hw1);
    cudaGetSymbolAddress((void**)&hw2,  g_hw2);
    cudaGetSymbolAddress((void**)&hh1,  g_hh1);
    cudaGetSymbolAddress((void**)&h1h,  g_h1h);
    cudaGetSymbolAddress((void**)&hh2,  g_hh2);

    // fork: CSR prep on cudaStreamPerThread, f2h+GEMM1 on the main stream
    cudaEvent_t ev_fork, ev_join;
    cudaEventCreateWithFlags(&ev_fork, cudaEventDisableTiming);
    cudaEventCreateWithFlags(&ev_join, cudaEventDisableTiming);
    cudaEventRecord(ev_fork, 0);
    cudaStreamWaitEvent(cudaStreamPerThread, ev_fork, 0);

    // ---- prep chain (per-thread stream) ----
    k_detect<<<1, 256, 0, cudaStreamPerThread>>>((const int*)ei, 8192);
    k_zeroint<<<(n + 255) / 256, 256, 0, cudaStreamPerThread>>>(deg, n);
    k_edgedeg<<<(E + 255) / 256, 256, 0, cudaStreamPerThread>>>(ei, deg, E);
    k_scan1<<<NBLK, SCAN_B, 0, cudaStreamPerThread>>>(deg, off, bsum);
    k_scan2<<<1, 64, 0, cudaStreamPerThread>>>(bsum, off + NN);
    k_scan3<<<NBLK, SCAN_B, 0, cudaStreamPerThread>>>(off, cur, bsum, deg, dinv);
    k_bucket<<<(E + 255) / 256, 256, 0, cudaStreamPerThread>>>(ei, cur, srcs, E);
    cudaEventRecord(ev_join, cudaStreamPerThread);

    // ---- main stream: fp16 convert + unscaled GEMM1 (no dinv dependency) ----
    {
        int nx = n * F1 / 4, n1 = 256 * F1 / 4, n2 = 256 * F2 / 4;
        k_f2h3<<<(nx + n1 + n2 + 255) / 256, 256>>>(
            (const float4*)x, (uint2*)hx, nx,
            (const float4*)W1, (uint2*)hw1, n1,
            (const float4*)W2, (uint2*)hw2, n2);
    }
    const int MT = (n + 127) / 128;   // 391 row tiles
    {
        dim3 grid(F1 / 128, MT);
        k_gemm_h<<<grid, 256>>>(hx, hw1, (const float*)nullptr, hh1, n, F1);
    }

    // join: gather1 needs both GEMM1 output and the CSR/dinv
    cudaStreamWaitEvent(0, ev_join, 0);

    // ---- layer 1 gather (applies dinv[src] per edge, dinv[node] outer) ----
    k_gather_h<8, true, true, true><<<(n * 32 + 255) / 256, 256>>>(off, srcs, hh1, dinv, b1, h1h);

    // ---- layer 2 ----
    {
        dim3 grid(F2 / 128, MT);
        k_gemm_h<<<grid, 256>>>(h1h, hw2, dinv, hh2, n, F2);
    }
    k_gather_h<4, false, false, false><<<(n * 32 + 255) / 256, 256>>>(off, srcs, hh2, dinv, b2, d_out);

    cudaEventDestroy(ev_fork);
    cudaEventDestroy(ev_join);
}

// round 11
// speedup vs baseline: 1.0435x; 1.0435x over previous
#include <cuda_runtime.h>
#include <cuda_fp16.h>
#include <cstdint>

#define NN 50000
#define F1 256
#define F2 128
#define EMAX 2000000
#define SCAN_B 1024
#define NBLK ((NN + SCAN_B - 1) / SCAN_B)   // 49

// -------- scratch (static device globals; no allocation) --------
__device__ int g_deg[NN];
__device__ int g_off[NN + 1];
__device__ int g_cur[NN];
__device__ int g_bsum[NBLK];
__device__ int g_ctr;
__device__ int g_srcs[EMAX];
__device__ __align__(16) float  g_dinv[NN];
__device__ __align__(16) __half g_hx [(size_t)NN * F1];   // fp16 x
__device__ __align__(16) __half g_hw1[256 * F1];          // fp16 W1
__device__ __align__(16) __half g_hw2[256 * F2];          // fp16 W2
__device__ __align__(16) __half g_hh1[(size_t)NN * F1];   // fp16 (x@W1)*dinv
__device__ __align__(16) __half g_h1h[(size_t)NN * F1];   // fp16 relu'd layer-1 out
__device__ __align__(16) __half g_hh2[(size_t)NN * F2];   // fp16 (h1@W2)*dinv
// 1 if edge_index is int64. Static init; only ever overwritten with 0 when the
// data is int32 — same inputs give the same value every call (deterministic).
__device__ int g_is64 = 1;

__device__ __forceinline__ uint32_t smem_u32(const void* p) {
    uint32_t a;
    asm("{ .reg .u64 t; cvta.to.shared.u64 t, %1; cvt.u32.u64 %0, t; }" : "=r"(a) : "l"(p));
    return a;
}

#define MMA16816(d, a0, a1, a2, a3, b0, b1)                                   \
    asm volatile(                                                             \
        "mma.sync.aligned.m16n8k16.row.col.f32.f16.f16.f32 "                  \
        "{%0,%1,%2,%3}, {%4,%5,%6,%7}, {%8,%9}, {%0,%1,%2,%3};"               \
        : "+f"((d)[0]), "+f"((d)[1]), "+f"((d)[2]), "+f"((d)[3])              \
        : "r"(a0), "r"(a1), "r"(a2), "r"(a3), "r"(b0), "r"(b1))

#define LDSM_X4(r0, r1, r2, r3, addr)                                         \
    asm volatile("ldmatrix.sync.aligned.m8n8.x4.shared.b16 {%0,%1,%2,%3}, [%4];" \
        : "=r"(r0), "=r"(r1), "=r"(r2), "=r"(r3) : "r"(addr))

#define LDSM_X4_T(r0, r1, r2, r3, addr)                                       \
    asm volatile("ldmatrix.sync.aligned.m8n8.x4.trans.shared.b16 {%0,%1,%2,%3}, [%4];" \
        : "=r"(r0), "=r"(r1), "=r"(r2), "=r"(r3) : "r"(addr))

__device__ __forceinline__ void cvt4(const float4* s, uint2* d, int j) {
    float4 v = s[j];
    __half2 h0 = __floats2half2_rn(v.x, v.y);
    __half2 h1 = __floats2half2_rn(v.z, v.w);
    uint2 o;
    o.x = *(uint32_t*)&h0;
    o.y = *(uint32_t*)&h1;
    d[j] = o;
}

// ======== k_init: detect dtype + zero deg + reset scan ctr + f2h x/W1/W2 ====
__global__ void k_init(const float4* __restrict__ x, uint2* __restrict__ hx, int nx,
                       const float4* __restrict__ w1, uint2* __restrict__ hw1, int n1,
                       const float4* __restrict__ w2, uint2* __restrict__ hw2, int n2,
                       int* __restrict__ deg, const int* __restrict__ ew, int ndet)
{
    int i = blockIdx.x * blockDim.x + threadIdx.x;
    if (i == 0) g_ctr = 0;
    if (i < nx) { cvt4(x, hx, i); return; }
    i -= nx;
    if (i < n1) { cvt4(w1, hw1, i); return; }
    i -= n1;
    if (i < n2) { cvt4(w2, hw2, i); return; }
    i -= n2;
    if (i < NN / 4) { ((int4*)deg)[i] = make_int4(0, 0, 0, 0); return; }
    i -= NN / 4;
    if (i < ndet) {
        // int64 edges (<50000) -> every odd 32-bit word is 0. Any nonzero odd
        // word proves int32.
        if (ew[2 * i + 1] != 0) atomicExch(&g_is64, 0);
    }
}

// -------- per-dst edge degree (32-bit low-word loads) --------
__global__ void k_edgedeg(const int* __restrict__ ew, int* __restrict__ deg, int E) {
    int i = blockIdx.x * blockDim.x + threadIdx.x;
    if (i >= E) return;
    int d = g_is64 ? ew[2 * (E + i)] : ew[E + i];
    atomicAdd(deg + d, 1);
}

// ======== fused single-launch exclusive scan + cur + dinv ========
// 49 blocks, all co-resident (49 <= 148 SMs) -> arrive-counter spin is safe.
__global__ __launch_bounds__(SCAN_B) void k_scan_fused(
    const int* __restrict__ deg, int* __restrict__ off, int* __restrict__ cur,
    float* __restrict__ dinv)
{
    __shared__ int sh[SCAN_B];
    __shared__ int bs[64];
    int t = threadIdx.x;
    int b = blockIdx.x;
    int idx = b * SCAN_B + t;
    int v = (idx < NN) ? deg[idx] : 0;
    sh[t] = v;
    __syncthreads();
#pragma unroll
    for (int d = 1; d < SCAN_B; d <<= 1) {
        int u = 0;
        if (t >= d) u = sh[t - d];
        __syncthreads();
        if (t >= d) sh[t] += u;
        __syncthreads();
    }
    int incl = sh[t];
    if (t == SCAN_B - 1) {
        g_bsum[b] = incl;            // block total
        __threadfence();             // publish before arriving
        atomicAdd(&g_ctr, 1);
    }
    if (t == 0) {
        while (atomicAdd(&g_ctr, 0) < NBLK) { }
        __threadfence();
    }
    __syncthreads();
    if (t < NBLK) bs[t] = __ldcg(&g_bsum[t]);   // L1-bypassing read
    __syncthreads();
    int carry = 0;
    for (int j = 0; j < b; j++) carry += bs[j]; // uniform smem reads (broadcast)
    int o = incl - v + carry;
    if (idx < NN) {
        off[idx] = o;
        cur[idx] = o;
        dinv[idx] = rsqrtf((float)deg[idx] + 1.0f);
    }
    if (b == NBLK - 1 && t == SCAN_B - 1) off[NN] = carry + incl;  // == E
}

// -------- counting-sort bucket fill (32-bit low-word loads) --------
__global__ void k_bucket(const int* __restrict__ ew, int* __restrict__ cur,
                         int* __restrict__ srcs, int E) {
    int i = blockIdx.x * blockDim.x + threadIdx.x;
    if (i >= E) return;
    int is64 = g_is64;
    int s = is64 ? ew[2 * i] : ew[i];
    int d = is64 ? ew[2 * (E + i)] : ew[E + i];
    int p = atomicAdd(cur + d, 1);
    srcs[p] = s;
}

// ======== fp16 HMMA GEMM: Ch = half((Ah@Bh) * dinv[row]),  K=256 ========
__global__ __launch_bounds__(256) void k_gemm_h(
    const __half* __restrict__ Ah, const __half* __restrict__ Bh,
    const float* __restrict__ dinv, __half* __restrict__ Ch, int M, int N)
{
    constexpr int K = 256;
    constexpr int LDA = 40;                 // halfs: 32 + 8 pad (80B stride)
    constexpr int LDB = 136;                // halfs: 128 + 8 pad (272B stride)
    __shared__ __half As[2][128][LDA];
    __shared__ __half Bs[2][32][LDB];

    int tid = threadIdx.x;
    int w = tid >> 5;
    int lane = tid & 31;
    int gid = lane >> 2;
    int tig = lane & 3;
    int warp_m = w >> 2;                    // 0..1
    int warp_n = w & 3;                     // 0..3
    int row0 = blockIdx.y * 128;
    int col0 = blockIdx.x * 128;

    uint32_t asb = smem_u32(&As[0][0][0]);
    uint32_t bsb = smem_u32(&Bs[0][0][0]);

    float acc[4][4][4];
#pragma unroll
    for (int mt = 0; mt < 4; mt++)
#pragma unroll
        for (int nt = 0; nt < 4; nt++)
#pragma unroll
            for (int q = 0; q < 4; q++) acc[mt][nt][q] = 0.f;

    uint4 ra[2], rb[2];

    auto ldregs = [&](int kt) {
#pragma unroll
        for (int i = 0; i < 2; i++) {
            int u = tid + (i << 8);
            int r = u >> 2, c = (u & 3) * 8;
            int grow = row0 + r;
            ra[i] = (grow < M) ? *(const uint4*)(Ah + (size_t)grow * K + kt + c)
                               : make_uint4(0u, 0u, 0u, 0u);
            int k = u >> 4, cb = (u & 15) * 8;
            rb[i] = *(const uint4*)(Bh + (size_t)(kt + k) * N + col0 + cb);
        }
    };
    auto sts = [&](int b) {
#pragma unroll
        for (int i = 0; i < 2; i++) {
            int u = tid + (i << 8);
            *(uint4*)&As[b][u >> 2][(u & 3) * 8] = ra[i];
            *(uint4*)&Bs[b][u >> 4][(u & 15) * 8] = rb[i];
        }
    };
    auto mmabuf = [&](int b) {
#pragma unroll
        for (int k2 = 0; k2 < 32; k2 += 16) {
            uint32_t bf[4][2];
#pragma unroll
            for (int np = 0; np < 2; np++) {
                int brow = k2 + ((lane >> 3) & 1) * 8 + (lane & 7);
                int bcol = warp_n * 32 + np * 16 + (lane >> 4) * 8;
                uint32_t ad = bsb + (uint32_t)(((b << 5) + brow) * LDB + bcol) * 2;
                LDSM_X4_T(bf[np * 2][0], bf[np * 2][1], bf[np * 2 + 1][0], bf[np * 2 + 1][1], ad);
            }
#pragma unroll
            for (int mt = 0; mt < 4; mt++) {
                int arow = warp_m * 64 + mt * 16 + (lane & 15);
                int kc = k2 + (lane >> 4) * 8;
                uint32_t ad = asb + (uint32_t)(((b << 7) + arow) * LDA + kc) * 2;
                uint32_t a0, a1, a2, a3;
                LDSM_X4(a0, a1, a2, a3, ad);
#pragma unroll
                for (int nt = 0; nt < 4; nt++)
                    MMA16816(acc[mt][nt], a0, a1, a2, a3, bf[nt][0], bf[nt][1]);
            }
        }
    };

    ldregs(0);
    sts(0);
    __syncthreads();
#pragma unroll
    for (int ch = 0; ch < K / 32; ch++) {
        if (ch < K / 32 - 1) ldregs((ch + 1) * 32);
        mmabuf(ch & 1);
        if (ch < K / 32 - 1) sts((ch + 1) & 1);
        __syncthreads();
    }

#pragma unroll
    for (int mt = 0; mt < 4; mt++) {
        int r0 = row0 + warp_m * 64 + mt * 16 + gid;
        int r1 = r0 + 8;
        float s0 = (r0 < M) ? dinv[r0] : 0.f;
        float s1 = (r1 < M) ? dinv[r1] : 0.f;
#pragma unroll
        for (int nt = 0; nt < 4; nt++) {
            int c = col0 + warp_n * 32 + nt * 8 + tig * 2;
            if (r0 < M) {
                __half2 h = __floats2half2_rn(acc[mt][nt][0] * s0, acc[mt][nt][1] * s0);
                *(__half2*)(Ch + (size_t)r0 * N + c) = h;
            }
            if (r1 < M) {
                __half2 h = __floats2half2_rn(acc[mt][nt][2] * s1, acc[mt][nt][3] * s1);
                *(__half2*)(Ch + (size_t)r1 * N + c) = h;
            }
        }
    }
}

// -------- CSR gather-reduce over fp16 features, fp32 accumulate --------
// OUTH: write fp16 (for layer-1 output feeding GEMM2); else fp32.
template <int FH, bool RELU, bool OUTH>
__global__ __launch_bounds__(256) void k_gather_h(
    const int* __restrict__ off, const int* __restrict__ srcs,
    const __half* __restrict__ hsh, const float* __restrict__ dinv,
    const float* __restrict__ bias, void* __restrict__ outv)
{
    constexpr int F = 32 * FH;
    int node = (blockIdx.x * blockDim.x + threadIdx.x) >> 5;
    int lane = threadIdx.x & 31;
    if (node >= NN) return;
    const __half* base = hsh + lane * FH;

    float acc[FH];
#pragma unroll
    for (int j = 0; j < FH; j++) acc[j] = 0.f;

    auto accum = [&](int s) {
        const __half* p = base + (size_t)s * F;
        if (FH == 8) {
            uint4 v = *(const uint4*)p;
            float2 f;
            f = __half22float2(*(__half2*)&v.x); acc[0] += f.x; acc[1] += f.y;
            f = __half22float2(*(__half2*)&v.y); acc[2] += f.x; acc[3] += f.y;
            f = __half22float2(*(__half2*)&v.z); acc[4] += f.x; acc[5] += f.y;
            f = __half22float2(*(__half2*)&v.w); acc[6] += f.x; acc[7] += f.y;
        } else {
            uint2 v = *(const uint2*)p;
            float2 f;
            f = __half22float2(*(__half2*)&v.x); acc[0] += f.x; acc[1] += f.y;
            f = __half22float2(*(__half2*)&v.y); acc[2] += f.x; acc[3] += f.y;
        }
    };

    accum(node);                                   // self loop
    int e = off[node], end = off[node + 1];
    for (; e + 4 <= end; e += 4) {
        int s0 = srcs[e], s1 = srcs[e + 1], s2 = srcs[e + 2], s3 = srcs[e + 3];
        accum(s0); accum(s1); accum(s2); accum(s3);
    }
    for (; e < end; e++) accum(srcs[e]);

    float sc = dinv[node];
    const float* bp = bias + lane * FH;
    float o[FH];
#pragma unroll
    for (int j = 0; j < FH; j += 4) {
        float4 b = *(const float4*)(bp + j);
        o[j + 0] = sc * acc[j + 0] + b.x;
        o[j + 1] = sc * acc[j + 1] + b.y;
        o[j + 2] = sc * acc[j + 2] + b.z;
        o[j + 3] = sc * acc[j + 3] + b.w;
        if (RELU) {
            o[j + 0] = fmaxf(o[j + 0], 0.f); o[j + 1] = fmaxf(o[j + 1], 0.f);
            o[j + 2] = fmaxf(o[j + 2], 0.f); o[j + 3] = fmaxf(o[j + 3], 0.f);
        }
    }
    if (OUTH) {
        __half* dst = (__half*)outv + (size_t)node * F + lane * FH;
#pragma unroll
        for (int j = 0; j < FH; j += 4) {
            __half2 h0 = __floats2half2_rn(o[j + 0], o[j + 1]);
            __half2 h1 = __floats2half2_rn(o[j + 2], o[j + 3]);
            uint2 hp;
            hp.x = *(uint32_t*)&h0;
            hp.y = *(uint32_t*)&h1;
            *(uint2*)(dst + j) = hp;
        }
    } else {
        float* dst = (float*)outv + (size_t)node * F + lane * FH;
#pragma unroll
        for (int j = 0; j < FH; j += 4) {
            float4 v = make_float4(o[j + 0], o[j + 1], o[j + 2], o[j + 3]);
            *(float4*)(dst + j) = v;
        }
    }
}

extern "C" void kernel_launch(void* const* d_in, const int* in_sizes, int n_in,
                              void* d_out, int out_size)
{
    const float* x  = (const float*)d_in[0];
    const int*   ew = (const int*)d_in[1];   // edge words (int32 view)
    const float* W1 = (const float*)d_in[2];
    const float* b1 = (const float*)d_in[3];
    const float* W2 = (const float*)d_in[4];
    const float* b2 = (const float*)d_in[5];
    const int E = in_sizes[1] / 2;
    const int n = NN;

    int *deg, *off, *cur, *srcs;
    float *dinv;
    __half *hx, *hw1, *hw2, *hh1, *h1h, *hh2;
    cudaGetSymbolAddress((void**)&deg,  g_deg);
    cudaGetSymbolAddress((void**)&off,  g_off);
    cudaGetSymbolAddress((void**)&cur,  g_cur);
    cudaGetSymbolAddress((void**)&srcs, g_srcs);
    cudaGetSymbolAddress((void**)&dinv, g_dinv);
    cudaGetSymbolAddress((void**)&hx,   g_hx);
    cudaGetSymbolAddress((void**)&hw1,  g_hw1);
    cudaGetSymbolAddress((void**)&hw2,  g_hw2);
    cudaGetSymbolAddress((void**)&hh1,  g_hh1);
    cudaGetSymbolAddress((void**)&h1h,  g_h1h);
    cudaGetSymbolAddress((void**)&hh2,  g_hh2);

    // ---- fused init: detect + zero deg + ctr reset + fp16 conversions ----
    const int nx = n * F1 / 4, n1 = 256 * F1 / 4, n2 = 256 * F2 / 4;
    const int ndet = 4096;
    const int tot = nx + n1 + n2 + NN / 4 + ndet;
    k_init<<<(tot + 255) / 256, 256>>>(
        (const float4*)x, (uint2*)hx, nx,
        (const float4*)W1, (uint2*)hw1, n1,
        (const float4*)W2, (uint2*)hw2, n2,
        deg, ew, ndet);

    // ---- CSR prep: degrees -> fused scan -> buckets ----
    k_edgedeg<<<(E + 255) / 256, 256>>>(ew, deg, E);
    k_scan_fused<<<NBLK, SCAN_B>>>(deg, off, cur, dinv);
    k_bucket<<<(E + 255) / 256, 256>>>(ew, cur, srcs, E);

    const int MT = (n + 127) / 128;   // 391 row tiles

    // ---- layer 1 ----
    {
        dim3 grid(F1 / 128, MT);
        k_gemm_h<<<grid, 256>>>(hx, hw1, dinv, hh1, n, F1);
    }
    k_gather_h<8, true, true><<<(n * 32 + 255) / 256, 256>>>(off, srcs, hh1, dinv, b1, h1h);

    // ---- layer 2 ----
    {
        dim3 grid(F2 / 128, MT);
        k_gemm_h<<<grid, 256>>>(h1h, hw2, dinv, hh2, n, F2);
    }
    k_gather_h<4, false, false><<<(n * 32 + 255) / 256, 256>>>(off, srcs, hh2, dinv, b2, d_out);
}